// round 10
// baseline (speedup 1.0000x reference)
#include <cuda_runtime.h>

#define NB 16
#define NS 4
#define NK 11
#define NBS (NB * NS)         // 64
#define NBSK (NB * NS * NK)   // 704
#define NTHR 256

// Scratch: per-(b,s,k) partials + per-(b,s) arrival counters. Static device
// globals (no allocation). Counters zero at load; finisher resets them each
// launch so graph replays stay deterministic.
__device__ float    g_part[2 * NBSK];
__device__ unsigned g_cnt[NBS];

// RELEASE-only atomic: orders prior .cg stores; no acquire half -> no
// CCTL.IVALL (L1 invalidate). Reader uses ld.cg so no acquire needed.
__device__ __forceinline__ unsigned atom_add_release_gpu(unsigned* p, unsigned v)
{
    unsigned old;
    asm volatile("atom.release.gpu.global.add.u32 %0, [%1], %2;"
                 : "=r"(old) : "l"(p), "r"(v) : "memory");
    return old;
}

// 256 threads x 5 CTAs/SM = 40 warps/SM (occ ~62%), and 704 <= 148*5 = 740
// slots so the whole grid is ONE resident wave. launch_bounds caps regs at 51.
__global__ void __launch_bounds__(NTHR, 5)
keypoint_main_kernel(const float* __restrict__ cp,     // (16,4,22,128,128)
                     const float* __restrict__ heat,   // (16,11,128,128)
                     const float* __restrict__ lab,    // (16,11,11)
                     float* __restrict__ out)          // 128 floats
{
    const int bsk = blockIdx.x;          // 0..703
    const int k   = bsk % NK;
    const int bs  = bsk / NK;            // b*4+s
    const int b   = bs >> 2;

    const float4* __restrict__ hptr =
        (const float4*)(cp + ((size_t)(bs * 22 + k) << 14));
    const float4* __restrict__ gptr =
        (const float4*)(heat + ((size_t)(b * NK + k) << 14));

    const int t = threadIdx.x;           // 0..255

    float s0 = 0.0f, s1 = 0.0f, s2 = 0.0f, s3 = 0.0f;
    float mx   = -__int_as_float(0x7f800000); // -inf
    int   bwin = 0;                           // winning batch id
    // latched values of the winning batch (8 floats)
    float w0 = 0, w1 = 0, w2 = 0, w3 = 0, w4 = 0, w5 = 0, w6 = 0, w7 = 0;

    // 4096 float4/map / 256 thr = 16 f4 per thread per stream.
    // 8 batches of (2 h + 2 g) float4. Argmax via batch-max (FMNMX tree) +
    // select-latch: no predicate-guard chains in the hot loop.
    #pragma unroll
    for (int j = 0; j < 8; j++) {
        const int v0 = t + (j * 2 + 0) * NTHR;
        const int v1 = t + (j * 2 + 1) * NTHR;
        const float4 h0 = hptr[v0];
        const float4 g0 = gptr[v0];
        const float4 h1 = hptr[v1];
        const float4 g1 = gptr[v1];

        float d0 = h0.x - g0.x, d1 = h0.y - g0.y;
        float d2 = h0.z - g0.z, d3 = h0.w - g0.w;
        float e0 = h1.x - g1.x, e1 = h1.y - g1.y;
        float e2 = h1.z - g1.z, e3 = h1.w - g1.w;
        s0 = fmaf(d0, d0, s0); s1 = fmaf(d1, d1, s1);
        s2 = fmaf(d2, d2, s2); s3 = fmaf(d3, d3, s3);
        s0 = fmaf(e0, e0, s0); s1 = fmaf(e1, e1, s1);
        s2 = fmaf(e2, e2, s2); s3 = fmaf(e3, e3, s3);

        // batch max of the 8 h-values (FMNMX tree, no predicates)
        const float m01 = fmaxf(fmaxf(h0.x, h0.y), fmaxf(h0.z, h0.w));
        const float m23 = fmaxf(fmaxf(h1.x, h1.y), fmaxf(h1.z, h1.w));
        const float mb  = fmaxf(m01, m23);

        // strict > keeps the earliest batch on ties (first occurrence)
        const bool take = (mb > mx);
        mx   = take ? mb : mx;
        bwin = take ? j  : bwin;
        w0 = take ? h0.x : w0;  w1 = take ? h0.y : w1;
        w2 = take ? h0.z : w2;  w3 = take ? h0.w : w3;
        w4 = take ? h1.x : w4;  w5 = take ? h1.y : w5;
        w6 = take ? h1.z : w6;  w7 = take ? h1.w : w7;
    }
    float sum = (s0 + s1) + (s2 + s3);

    // Reconstruct first-occurrence global index within the winning batch.
    // Ascending scan -> earliest position with value == mx.
    const int base0 = (t + (bwin * 2 + 0) * NTHR) << 2;
    const int base1 = (t + (bwin * 2 + 1) * NTHR) << 2;
    int mi;
    if      (w0 == mx) mi = base0;
    else if (w1 == mx) mi = base0 + 1;
    else if (w2 == mx) mi = base0 + 2;
    else if (w3 == mx) mi = base0 + 3;
    else if (w4 == mx) mi = base1;
    else if (w5 == mx) mi = base1 + 1;
    else if (w6 == mx) mi = base1 + 2;
    else               mi = base1 + 3;

    // Warp reduce (sum, argmax with lowest-index tiebreak)
    #pragma unroll
    for (int off = 16; off > 0; off >>= 1) {
        float osum = __shfl_down_sync(0xffffffffu, sum, off);
        float omx  = __shfl_down_sync(0xffffffffu, mx,  off);
        int   omi  = __shfl_down_sync(0xffffffffu, mi,  off);
        sum += osum;
        if (omx > mx || (omx == mx && omi < mi)) { mx = omx; mi = omi; }
    }

    __shared__ float ssum[8];
    __shared__ float smx[8];
    __shared__ int   smi[8];
    const int w = t >> 5, l = t & 31;
    if (l == 0) { ssum[w] = sum; smx[w] = mx; smi[w] = mi; }
    __syncthreads();

    if (t == 0) {
        #pragma unroll
        for (int w2i = 1; w2i < 8; w2i++) {
            sum += ssum[w2i];
            if (smx[w2i] > mx || (smx[w2i] == mx && smi[w2i] < mi)) {
                mx = smx[w2i]; mi = smi[w2i];
            }
        }

        // ---- label-loss term for this (b,s,k) ----
        const float* __restrict__ lp =
            cp + ((size_t)(bs * 22 + NK + k) << 14);     // lb map, first 9 used
        const float* __restrict__ lb = lab + (size_t)(b * NK + k) * 11;

        const float gx = lb[9];
        const float gy = lb[10];
        const bool valid = (gx > 0.0f) && (gy > 0.0f) &&
                           (gx < 128.0f) && (gy < 128.0f);

        const float xf = (float)(mi >> 7);    // index // 128
        const float yf = (float)(mi & 127);   // index % 128

        const float dx = gx + lb[7] - xf - lp[7];
        const float dy = gy + lb[8] - yf - lp[8];
        const float xy_loss = dx * dx + dy * dy;

        const float c = 1.0f - mx;
        const float conf_loss = c * c;

        float cls = 0.0f;
        #pragma unroll
        for (int j = 0; j < 7; j++) {
            const float d = lp[j] - lb[j];
            cls = fmaf(d, d, cls);
        }

        // L1-bypass stores: land in L2, visible to any finisher on any SM.
        __stcg(&g_part[bsk], sum);
        __stcg(&g_part[NBSK + bsk],
               valid ? (cls + xy_loss + conf_loss) : 0.0f);

        // Release-only ordering; reader uses ld.cg (L1-bypass).
        const unsigned prev = atom_add_release_gpu(&g_cnt[bs], 1u);
        if (prev == NK - 1) {
            g_cnt[bs] = 0;               // reset for next graph replay
            float hsum = 0.0f, lsum = 0.0f;
            #pragma unroll
            for (int kk = 0; kk < NK; kk++) {
                hsum += __ldcg(&g_part[bs * NK + kk]);
                lsum += __ldcg(&g_part[NBSK + bs * NK + kk]);
            }
            out[bs]      = hsum;         // heat_loss (16,4)
            out[64 + bs] = lsum;         // label_loss (16,4)
        }
    }
}

extern "C" void kernel_launch(void* const* d_in, const int* in_sizes, int n_in,
                              void* d_out, int out_size)
{
    const float* cp   = (const float*)d_in[0]; // combined_preds
    const float* heat = (const float*)d_in[1]; // heatmaps
    const float* lab  = (const float*)d_in[2]; // labels
    float* out = (float*)d_out;

    keypoint_main_kernel<<<NBSK, NTHR>>>(cp, heat, lab, out);
}

// round 11
// speedup vs baseline: 1.1493x; 1.1493x over previous
#include <cuda_runtime.h>

#define NB 16
#define NS 4
#define NK 11
#define NQ 4
#define NTHR 128
#define NCTA (NB * NK * NQ)     // 704
#define NPART (NB * NK * NQ * NS) // 2816

// Per-(b,k,q,s) quarter partials + per-b arrival counters. Static device
// globals (no allocation). Counters zero at load; finisher resets them.
__device__ float    g_qsum[NPART];
__device__ float    g_qmx [NPART];
__device__ int      g_qmi [NPART];
__device__ unsigned g_cnt [NB];

// RELEASE-only atomic: orders prior .cg stores; no acquire half -> no
// CCTL.IVALL (L1 invalidate). Readers use ld.cg so no acquire needed.
__device__ __forceinline__ unsigned atom_add_release_gpu(unsigned* p, unsigned v)
{
    unsigned old;
    asm volatile("atom.release.gpu.global.add.u32 %0, [%1], %2;"
                 : "=r"(old) : "l"(p), "r"(v) : "memory");
    return old;
}

// CTA = (b, k, quarter), processes all 4 stacks s against ONE g-quarter load.
// 704 CTAs x 128 thr, <=5 CTAs/SM resident: whole grid in ONE wave.
__global__ void __launch_bounds__(NTHR, 5)
keypoint_main_kernel(const float* __restrict__ cp,     // (16,4,22,128,128)
                     const float* __restrict__ heat,   // (16,11,128,128)
                     const float* __restrict__ lab,    // (16,11,11)
                     float* __restrict__ out)          // 128 floats
{
    const int cta = blockIdx.x;          // 0..703
    const int q   = cta & 3;             // spatial quarter
    const int k   = (cta >> 2) % NK;
    const int b   = cta / (NK * NQ);

    const int t = threadIdx.x;           // 0..127

    // g quarter for (b,k): 1024 float4
    const float4* __restrict__ gq =
        (const float4*)(heat + (((size_t)(b * NK + k)) << 14)) + (q << 10);
    // h quarters for s = 0..3
    const float4* __restrict__ hq0 =
        (const float4*)(cp + (((size_t)((b * NS + 0) * 22 + k)) << 14)) + (q << 10);
    const float4* __restrict__ hq1 =
        (const float4*)(cp + (((size_t)((b * NS + 1) * 22 + k)) << 14)) + (q << 10);
    const float4* __restrict__ hq2 =
        (const float4*)(cp + (((size_t)((b * NS + 2) * 22 + k)) << 14)) + (q << 10);
    const float4* __restrict__ hq3 =
        (const float4*)(cp + (((size_t)((b * NS + 3) * 22 + k)) << 14)) + (q << 10);

    float sum0 = 0, sum1 = 0, sum2 = 0, sum3 = 0;
    const float NEG_INF = -__int_as_float(0x7f800000);
    float mx0 = NEG_INF, mx1 = NEG_INF, mx2 = NEG_INF, mx3 = NEG_INF;
    int   mi0 = 0, mi1 = 0, mi2 = 0, mi3 = 0;

    // 1024 f4 per quarter / 128 thr = 8 iterations; per iter: 1 g + 4 h LDG.128.
    #pragma unroll
    for (int it = 0; it < 8; it++) {
        const int v = t + it * NTHR;         // f4 index in quarter [0,1024)
        const float4 g  = gq[v];
        const float4 h0 = hq0[v];
        const float4 h1 = hq1[v];
        const float4 h2 = hq2[v];
        const float4 h3 = hq3[v];
        const int base = (q << 12) + (v << 2);   // global flat index in map

        // s = 0
        {
            float d0 = h0.x - g.x, d1 = h0.y - g.y, d2 = h0.z - g.z, d3 = h0.w - g.w;
            sum0 = fmaf(d0, d0, sum0); sum0 = fmaf(d1, d1, sum0);
            sum0 = fmaf(d2, d2, sum0); sum0 = fmaf(d3, d3, sum0);
            if (h0.x > mx0) { mx0 = h0.x; mi0 = base; }
            if (h0.y > mx0) { mx0 = h0.y; mi0 = base + 1; }
            if (h0.z > mx0) { mx0 = h0.z; mi0 = base + 2; }
            if (h0.w > mx0) { mx0 = h0.w; mi0 = base + 3; }
        }
        // s = 1
        {
            float d0 = h1.x - g.x, d1 = h1.y - g.y, d2 = h1.z - g.z, d3 = h1.w - g.w;
            sum1 = fmaf(d0, d0, sum1); sum1 = fmaf(d1, d1, sum1);
            sum1 = fmaf(d2, d2, sum1); sum1 = fmaf(d3, d3, sum1);
            if (h1.x > mx1) { mx1 = h1.x; mi1 = base; }
            if (h1.y > mx1) { mx1 = h1.y; mi1 = base + 1; }
            if (h1.z > mx1) { mx1 = h1.z; mi1 = base + 2; }
            if (h1.w > mx1) { mx1 = h1.w; mi1 = base + 3; }
        }
        // s = 2
        {
            float d0 = h2.x - g.x, d1 = h2.y - g.y, d2 = h2.z - g.z, d3 = h2.w - g.w;
            sum2 = fmaf(d0, d0, sum2); sum2 = fmaf(d1, d1, sum2);
            sum2 = fmaf(d2, d2, sum2); sum2 = fmaf(d3, d3, sum2);
            if (h2.x > mx2) { mx2 = h2.x; mi2 = base; }
            if (h2.y > mx2) { mx2 = h2.y; mi2 = base + 1; }
            if (h2.z > mx2) { mx2 = h2.z; mi2 = base + 2; }
            if (h2.w > mx2) { mx2 = h2.w; mi2 = base + 3; }
        }
        // s = 3
        {
            float d0 = h3.x - g.x, d1 = h3.y - g.y, d2 = h3.z - g.z, d3 = h3.w - g.w;
            sum3 = fmaf(d0, d0, sum3); sum3 = fmaf(d1, d1, sum3);
            sum3 = fmaf(d2, d2, sum3); sum3 = fmaf(d3, d3, sum3);
            if (h3.x > mx3) { mx3 = h3.x; mi3 = base; }
            if (h3.y > mx3) { mx3 = h3.y; mi3 = base + 1; }
            if (h3.z > mx3) { mx3 = h3.z; mi3 = base + 2; }
            if (h3.w > mx3) { mx3 = h3.w; mi3 = base + 3; }
        }
    }

    // Warp reduce each s (sum, argmax with lowest-index tiebreak)
    float sums[NS] = { sum0, sum1, sum2, sum3 };
    float mxs [NS] = { mx0, mx1, mx2, mx3 };
    int   mis [NS] = { mi0, mi1, mi2, mi3 };
    #pragma unroll
    for (int s = 0; s < NS; s++) {
        float sm = sums[s], mx = mxs[s];
        int   mi = mis[s];
        #pragma unroll
        for (int off = 16; off > 0; off >>= 1) {
            float os  = __shfl_down_sync(0xffffffffu, sm, off);
            float omx = __shfl_down_sync(0xffffffffu, mx, off);
            int   omi = __shfl_down_sync(0xffffffffu, mi, off);
            sm += os;
            if (omx > mx || (omx == mx && omi < mi)) { mx = omx; mi = omi; }
        }
        sums[s] = sm; mxs[s] = mx; mis[s] = mi;
    }

    __shared__ float ssum[4][NS];
    __shared__ float smx [4][NS];
    __shared__ int   smi [4][NS];
    __shared__ int   s_fin;
    const int w = t >> 5, l = t & 31;
    if (l == 0) {
        #pragma unroll
        for (int s = 0; s < NS; s++) {
            ssum[w][s] = sums[s]; smx[w][s] = mxs[s]; smi[w][s] = mis[s];
        }
    }
    __syncthreads();

    if (t == 0) {
        #pragma unroll
        for (int s = 0; s < NS; s++) {
            float sm = ssum[0][s], mx = smx[0][s];
            int   mi = smi[0][s];
            #pragma unroll
            for (int w2 = 1; w2 < 4; w2++) {
                sm += ssum[w2][s];
                if (smx[w2][s] > mx || (smx[w2][s] == mx && smi[w2][s] < mi)) {
                    mx = smx[w2][s]; mi = smi[w2][s];
                }
            }
            const int idx = ((b * NK + k) * NQ + q) * NS + s;
            __stcg(&g_qsum[idx], sm);
            __stcg(&g_qmx [idx], mx);
            __stcg(&g_qmi [idx], mi);
        }
        // Release orders the .cg stores above before the increment is seen.
        const unsigned prev = atom_add_release_gpu(&g_cnt[b], 1u);
        s_fin = (prev == NK * NQ - 1);
        if (s_fin) g_cnt[b] = 0;         // reset for next graph replay
    }
    __syncthreads();

    if (s_fin) {
        __shared__ float s_heat[NS * NK];
        __shared__ float s_lab [NS * NK];
        if (t < NS * NK) {               // 44 threads: tt = s*11 + k2
            const int s  = t / NK;
            const int k2 = t % NK;
            float hs = 0.0f;
            float mx = -__int_as_float(0x7f800000);
            int   mi = 0x7fffffff;
            #pragma unroll
            for (int qq = 0; qq < NQ; qq++) {
                const int idx = ((b * NK + k2) * NQ + qq) * NS + s;
                const float ps = __ldcg(&g_qsum[idx]);
                const float pm = __ldcg(&g_qmx [idx]);
                const int   pi = __ldcg(&g_qmi [idx]);
                hs += ps;
                if (pm > mx || (pm == mx && pi < mi)) { mx = pm; mi = pi; }
            }

            const int bs = b * NS + s;
            const float* __restrict__ lp =
                cp + (((size_t)(bs * 22 + NK + k2)) << 14);
            const float* __restrict__ lb = lab + (size_t)(b * NK + k2) * 11;

            const float gx = lb[9];
            const float gy = lb[10];
            const bool valid = (gx > 0.0f) && (gy > 0.0f) &&
                               (gx < 128.0f) && (gy < 128.0f);

            const float xf = (float)(mi >> 7);
            const float yf = (float)(mi & 127);

            const float dx = gx + lb[7] - xf - lp[7];
            const float dy = gy + lb[8] - yf - lp[8];
            const float xy_loss = dx * dx + dy * dy;

            const float c = 1.0f - mx;
            const float conf_loss = c * c;

            float cls = 0.0f;
            #pragma unroll
            for (int j = 0; j < 7; j++) {
                const float d = lp[j] - lb[j];
                cls = fmaf(d, d, cls);
            }

            s_heat[t] = hs;
            s_lab [t] = valid ? (cls + xy_loss + conf_loss) : 0.0f;
        }
        __syncthreads();
        if (t < NS) {                    // one thread per s
            float hsum = 0.0f, lsum = 0.0f;
            #pragma unroll
            for (int k2 = 0; k2 < NK; k2++) {
                hsum += s_heat[t * NK + k2];
                lsum += s_lab [t * NK + k2];
            }
            out[b * NS + t]      = hsum;   // heat_loss (16,4)
            out[64 + b * NS + t] = lsum;   // label_loss (16,4)
        }
    }
}

extern "C" void kernel_launch(void* const* d_in, const int* in_sizes, int n_in,
                              void* d_out, int out_size)
{
    const float* cp   = (const float*)d_in[0]; // combined_preds
    const float* heat = (const float*)d_in[1]; // heatmaps
    const float* lab  = (const float*)d_in[2]; // labels
    float* out = (float*)d_out;

    keypoint_main_kernel<<<NCTA, NTHR>>>(cp, heat, lab, out);
}